// round 5
// baseline (speedup 1.0000x reference)
#include <cuda_runtime.h>
#include <cstdint>

// ---------------------------------------------------------------------------
// DOMINANT 4-layer GCN autoencoder.
// CSR gather-based aggregation (warp-per-node, packed edges, no atomics in
// hot path) + packed-f32x2 (FFMA2) GEMMs.
//   L1: h=x@W1;            abuf = relu(A_hat h + b1)
//   L2: h=abuf@W2;         z    = relu(A_hat h + b2)
//   L3: h=z@W3;            abuf = relu(A_hat h + b3)
//   L4: hbuf=A_hat abuf;   x_hat = hbuf@W4 + b4        (A(XW) == (AX)W)
//   out = concat(x_hat[N,128], z[N,64])
// ---------------------------------------------------------------------------

#define MAXN 50048
#define MAXE 640000

__device__ float g_h[(size_t)MAXN * 64];    // post-GEMM features (D=64)
__device__ float g_buf[(size_t)MAXN * 64];  // layer outputs h1 / xh / agg4
__device__ float g_dis[MAXN];               // rsqrt(deg+1)
__device__ int   g_deg[MAXN];               // in-degree (edges only)
__device__ int   g_off[MAXN];               // CSR block-local exclusive offsets
__device__ int   g_cur[MAXN];               // scatter cursors
__device__ int   g_part[1024];              // scan block partials (exclusive)
__device__ int   g_src[MAXE];
__device__ int   g_dst[MAXE];
__device__ int2  g_epack[MAXE];             // CSR slot: (src, norm bits)
__device__ int   g_flag;                    // 1 => edge_index is int32

// ========================= graph prep kernels ==============================
// zero g_deg + g_cur; block 0 also detects edge dtype (int64 values all
// < 50000; int32 data reinterpreted as int64 yields values >= 2^32 w.h.p.)
__global__ void detect_zero_kernel(const long long* __restrict__ p, int cnt, int n) {
    int i = blockIdx.x * blockDim.x + threadIdx.x;
    if (i < n) { g_deg[i] = 0; g_cur[i] = 0; }
    if (blockIdx.x == 0) {
        __shared__ int bad;
        if (threadIdx.x == 0) bad = 0;
        __syncthreads();
        int lb = 0;
        for (int j = threadIdx.x; j < cnt; j += blockDim.x) {
            long long v = p[j];
            if (v < 0 || v > 0x7fffffffLL) lb = 1;
        }
        if (lb) atomicOr(&bad, 1);
        __syncthreads();
        if (threadIdx.x == 0) g_flag = bad;
    }
}

__global__ void decode_count_kernel(const void* __restrict__ ei, int E) {
    int e = blockIdx.x * blockDim.x + threadIdx.x;
    if (e >= E) return;
    int s, d;
    if (g_flag) {
        const int* p = (const int*)ei;
        s = p[e]; d = p[E + e];
    } else {
        const long long* p = (const long long*)ei;
        s = (int)p[e]; d = (int)p[(size_t)E + e];
    }
    g_src[e] = s;
    g_dst[e] = d;
    atomicAdd(&g_deg[d], 1);
}

// fused: g_dis = rsqrt(deg+1)  +  per-block exclusive scan of g_deg -> g_off
__global__ void dis_scan_kernel(int n) {
    __shared__ int sh[256];
    int i = blockIdx.x * 256 + threadIdx.x;
    int v = 0;
    if (i < n) {
        v = g_deg[i];
        g_dis[i] = rsqrtf((float)(v + 1));
    }
    sh[threadIdx.x] = v;
    __syncthreads();
#pragma unroll
    for (int ofs = 1; ofs < 256; ofs <<= 1) {
        int t = (threadIdx.x >= ofs) ? sh[threadIdx.x - ofs] : 0;
        __syncthreads();
        sh[threadIdx.x] += t;
        __syncthreads();
    }
    if (i < n) g_off[i] = sh[threadIdx.x] - v;
    if (threadIdx.x == 255) g_part[blockIdx.x] = sh[255];
}

__global__ void scan_part_kernel(int nb) {
    __shared__ int sh[1024];
    int v = (threadIdx.x < nb) ? g_part[threadIdx.x] : 0;
    sh[threadIdx.x] = v;
    __syncthreads();
#pragma unroll
    for (int ofs = 1; ofs < 1024; ofs <<= 1) {
        int t = (threadIdx.x >= ofs) ? sh[threadIdx.x - ofs] : 0;
        __syncthreads();
        sh[threadIdx.x] += t;
        __syncthreads();
    }
    if (threadIdx.x < nb) g_part[threadIdx.x] = sh[threadIdx.x] - v;
}

// scatter edges to CSR slots; final offset = g_off[d] + g_part[d>>8]
__global__ void csr_scatter_kernel(int E) {
    int e = blockIdx.x * blockDim.x + threadIdx.x;
    if (e >= E) return;
    int s = g_src[e];
    int d = g_dst[e];
    int pos = g_off[d] + g_part[d >> 8] + atomicAdd(&g_cur[d], 1);
    g_epack[pos] = make_int2(s, __float_as_int(g_dis[s] * g_dis[d]));
}

// ===================== packed-f32x2 GEMM ===================================
// Y[n,DOUT] = X[n,K] @ W[K,DOUT] (+b). 256 threads; thread tile R rows x 4
// cols held as 2 packed f32x2 accumulators per row.
// Dynamic smem: Ws[K*DOUT] floats, then Xs2[ROWS*K] u64 (x duplicated lo==hi).
template <int K, int DOUT, int R, bool BIAS>
__global__ __launch_bounds__(256) void gemm_kernel(
    const float* __restrict__ X, const float* __restrict__ W,
    const float* __restrict__ b, float* __restrict__ Y, int n)
{
    constexpr int CG = DOUT / 4;
    constexpr int RG = 256 / CG;
    constexpr int ROWS = RG * R;

    extern __shared__ char dyn[];
    float* Ws = (float*)dyn;                                  // K*DOUT floats
    unsigned long long* Xs2 = (unsigned long long*)(dyn + (size_t)K * DOUT * 4);

    const int t = threadIdx.x;
    const int row0 = blockIdx.x * ROWS;

    for (int i = t; i < K * DOUT / 4; i += 256)
        ((float4*)Ws)[i] = ((const float4*)W)[i];

    for (int i = t; i < ROWS * K / 4; i += 256) {
        int pos = i * 4;
        int r = pos / K;
        int k = pos % K;
        int gr = row0 + r;
        float4 v = make_float4(0.f, 0.f, 0.f, 0.f);
        if (gr < n) v = *(const float4*)&X[(size_t)gr * K + k];
        unsigned long long d0, d1, d2, d3;
        asm("mov.b64 %0, {%1, %1};" : "=l"(d0) : "f"(v.x));
        asm("mov.b64 %0, {%1, %1};" : "=l"(d1) : "f"(v.y));
        asm("mov.b64 %0, {%1, %1};" : "=l"(d2) : "f"(v.z));
        asm("mov.b64 %0, {%1, %1};" : "=l"(d3) : "f"(v.w));
        unsigned long long* p = &Xs2[r * K + k];
        p[0] = d0; p[1] = d1; p[2] = d2; p[3] = d3;
    }
    __syncthreads();

    const int cg = t % CG;
    const int rg = t / CG;

    unsigned long long acc[R][2];
#pragma unroll
    for (int r = 0; r < R; r++) { acc[r][0] = 0ull; acc[r][1] = 0ull; }

#pragma unroll 4
    for (int k = 0; k < K; k++) {
        ulonglong2 w = *(const ulonglong2*)&Ws[k * DOUT + cg * 4];
#pragma unroll
        for (int r = 0; r < R; r++) {
            unsigned long long x2 = Xs2[(rg * R + r) * K + k];
            asm("fma.rn.f32x2 %0, %1, %2, %0;" : "+l"(acc[r][0]) : "l"(x2), "l"(w.x));
            asm("fma.rn.f32x2 %0, %1, %2, %0;" : "+l"(acc[r][1]) : "l"(x2), "l"(w.y));
        }
    }

    float4 bb = make_float4(0.f, 0.f, 0.f, 0.f);
    if (BIAS) bb = *(const float4*)&b[cg * 4];

#pragma unroll
    for (int r = 0; r < R; r++) {
        int gr = row0 + rg * R + r;
        if (gr < n) {
            float o0, o1, o2, o3;
            asm("mov.b64 {%0, %1}, %2;" : "=f"(o0), "=f"(o1) : "l"(acc[r][0]));
            asm("mov.b64 {%0, %1}, %2;" : "=f"(o2), "=f"(o3) : "l"(acc[r][1]));
            *(float4*)&Y[(size_t)gr * DOUT + cg * 4] =
                make_float4(o0 + bb.x, o1 + bb.y, o2 + bb.z, o3 + bb.w);
        }
    }
}

// ===================== CSR gather aggregation ==============================
// Warp-per-node: lanes 0-15 = columns (float4 each) x edge-half 0,
// lanes 16-31 = same columns x edge-half 1; shfl_xor(16) combines halves.
// out[i] = (relu)(sum_e h[src_e]*norm_e + h[i]*dis_i^2 (+ b))
template <bool BIAS, bool RELU>
__global__ __launch_bounds__(256) void agg_gather_kernel(
    const float* __restrict__ H, const float* __restrict__ b,
    float* __restrict__ out, int n)
{
    int node = (blockIdx.x * 256 + threadIdx.x) >> 5;
    if (node >= n) return;
    int lane = threadIdx.x & 31;
    int c = lane & 15;
    int half = lane >> 4;

    const float4* H4 = (const float4*)H;

    // self-loop row load issued early (overlaps edge loop)
    float dis = g_dis[node];
    float s2 = dis * dis;
    float4 hv = H4[(size_t)node * 16 + c];

    int beg = g_off[node] + g_part[node >> 8];
    int deg = g_deg[node];
    int end = beg + deg;

    float4 acc = make_float4(0.f, 0.f, 0.f, 0.f);

    int e = beg + half;
    // 2-deep per half -> 4 H-loads in flight per node-column
    for (; e + 2 < end; e += 4) {
        int2 p0 = g_epack[e];
        int2 p1 = g_epack[e + 2];
        float4 h0 = H4[(size_t)p0.x * 16 + c];
        float4 h1 = H4[(size_t)p1.x * 16 + c];
        float n0 = __int_as_float(p0.y);
        float n1 = __int_as_float(p1.y);
        acc.x += h0.x * n0; acc.y += h0.y * n0;
        acc.z += h0.z * n0; acc.w += h0.w * n0;
        acc.x += h1.x * n1; acc.y += h1.y * n1;
        acc.z += h1.z * n1; acc.w += h1.w * n1;
    }
    for (; e < end; e += 2) {
        int2 p0 = g_epack[e];
        float4 h0 = H4[(size_t)p0.x * 16 + c];
        float n0 = __int_as_float(p0.y);
        acc.x += h0.x * n0; acc.y += h0.y * n0;
        acc.z += h0.z * n0; acc.w += h0.w * n0;
    }

    // combine halves
    acc.x += __shfl_xor_sync(0xffffffffu, acc.x, 16);
    acc.y += __shfl_xor_sync(0xffffffffu, acc.y, 16);
    acc.z += __shfl_xor_sync(0xffffffffu, acc.z, 16);
    acc.w += __shfl_xor_sync(0xffffffffu, acc.w, 16);

    // self loop + bias + relu
    acc.x += hv.x * s2; acc.y += hv.y * s2;
    acc.z += hv.z * s2; acc.w += hv.w * s2;
    if (BIAS) {
        float4 bb = *(const float4*)&b[c * 4];
        acc.x += bb.x; acc.y += bb.y; acc.z += bb.z; acc.w += bb.w;
    }
    if (RELU) {
        acc.x = fmaxf(acc.x, 0.f); acc.y = fmaxf(acc.y, 0.f);
        acc.z = fmaxf(acc.z, 0.f); acc.w = fmaxf(acc.w, 0.f);
    }
    if (half == 0)
        ((float4*)out)[(size_t)node * 16 + c] = acc;
}

static inline int ceil_div(long long a, int bsz) { return (int)((a + bsz - 1) / bsz); }

extern "C" void kernel_launch(void* const* d_in, const int* in_sizes, int n_in,
                              void* d_out, int out_size)
{
    const float* x  = (const float*)d_in[0];
    const void*  ei = d_in[1];
    const float* W1 = (const float*)d_in[2];
    const float* b1 = (const float*)d_in[3];
    const float* W2 = (const float*)d_in[4];
    const float* b2 = (const float*)d_in[5];
    const float* W3 = (const float*)d_in[6];
    const float* b3 = (const float*)d_in[7];
    const float* W4 = (const float*)d_in[8];
    const float* b4 = (const float*)d_in[9];

    const int N = in_sizes[0] / 128;
    const int E = in_sizes[1] / 2;

    float* out  = (float*)d_out;
    float* xhat = out;                       // [N,128]
    float* z    = out + (size_t)N * 128;     // [N,64]

    float* hbuf;  cudaGetSymbolAddress((void**)&hbuf, g_h);
    float* abuf;  cudaGetSymbolAddress((void**)&abuf, g_buf);

    // dynamic smem: Ws (K*DOUT*4) + Xs2 (ROWS*K*8)
    const int SM_L1 = 128 * 64 * 4 + 64 * 128 * 8;   // 96K
    const int SM_L2 = 64 * 64 * 4 + 64 * 64 * 8;     // 48K
    const int SM_L4 = 64 * 128 * 4 + 32 * 64 * 8;    // 48K
    static bool attr_done = false;
    if (!attr_done) {
        cudaFuncSetAttribute(gemm_kernel<128, 64, 4, false>,
                             cudaFuncAttributeMaxDynamicSharedMemorySize, SM_L1);
        cudaFuncSetAttribute(gemm_kernel<64, 64, 4, false>,
                             cudaFuncAttributeMaxDynamicSharedMemorySize, SM_L2);
        cudaFuncSetAttribute(gemm_kernel<64, 128, 4, true>,
                             cudaFuncAttributeMaxDynamicSharedMemorySize, SM_L4);
        attr_done = true;
    }

    const int nb = ceil_div(N, 256);
    const int ab = ceil_div(N, 8);           // agg: warp per node, 8 nodes/block

    // --- graph prep: 5 launches ---
    detect_zero_kernel<<<nb, 256>>>((const long long*)ei, 4096, N);
    decode_count_kernel<<<ceil_div(E, 256), 256>>>(ei, E);
    dis_scan_kernel<<<nb, 256>>>(N);
    scan_part_kernel<<<1, 1024>>>(nb);
    csr_scatter_kernel<<<ceil_div(E, 256), 256>>>(E);

    // --- layer 1 (6th launch -> profiled by ncu -s 5) ---
    gemm_kernel<128, 64, 4, false><<<ceil_div(N, 64), 256, SM_L1>>>(x, W1, nullptr, hbuf, N);
    agg_gather_kernel<true, true><<<ab, 256>>>(hbuf, b1, abuf, N);

    // --- layer 2 ---
    gemm_kernel<64, 64, 4, false><<<ceil_div(N, 64), 256, SM_L2>>>(abuf, W2, nullptr, hbuf, N);
    agg_gather_kernel<true, true><<<ab, 256>>>(hbuf, b2, z, N);

    // --- layer 3 ---
    gemm_kernel<64, 64, 4, false><<<ceil_div(N, 64), 256, SM_L2>>>(z, W3, nullptr, hbuf, N);
    agg_gather_kernel<true, true><<<ab, 256>>>(hbuf, b3, abuf, N);

    // --- layer 4: aggregate first (A(XW) == (AX)W), then GEMM to 128 ---
    agg_gather_kernel<false, false><<<ab, 256>>>(abuf, nullptr, hbuf, N);
    gemm_kernel<64, 128, 4, true><<<ceil_div(N, 32), 256, SM_L4>>>(hbuf, W4, b4, xhat, N);
}

// round 6
// speedup vs baseline: 1.0876x; 1.0876x over previous
#include <cuda_runtime.h>
#include <cstdint>

// ---------------------------------------------------------------------------
// DOMINANT 4-layer GCN autoencoder.
// CSR gather-based aggregation (16 threads/node, 4-deep unroll, no atomics
// in hot path) + packed-f32x2 (FFMA2) GEMMs.
//   L1: h=x@W1;            abuf = relu(A_hat h + b1)
//   L2: h=abuf@W2;         z    = relu(A_hat h + b2)
//   L3: h=z@W3;            abuf = relu(A_hat h + b3)
//   L4: hbuf=A_hat abuf;   x_hat = hbuf@W4 + b4        (A(XW) == (AX)W)
//   out = concat(x_hat[N,128], z[N,64])
// ---------------------------------------------------------------------------

#define MAXN 50048
#define MAXE 640000

__device__ float g_h[(size_t)MAXN * 64];    // post-GEMM features (D=64)
__device__ float g_buf[(size_t)MAXN * 64];  // layer outputs h1 / xh / agg4
__device__ float g_dis[MAXN];               // rsqrt(deg+1)
__device__ int   g_deg[MAXN];               // in-degree (edges only)
__device__ int   g_off[MAXN];               // CSR slot base per node
__device__ int   g_cur[MAXN];               // scatter cursors
__device__ int   g_src[MAXE];
__device__ int   g_dst[MAXE];
__device__ int2  g_epack[MAXE];             // CSR slot: (src, norm bits)
__device__ int   g_flag;                    // 1 => edge_index is int32
__device__ int   g_total;                   // global slot allocator

// ========================= graph prep kernels ==============================
// zero g_deg + g_cur + g_total; block 0 also detects edge dtype (int64 data
// has all values < 50000; int32 reinterpreted as int64 -> huge values).
__global__ void detect_zero_kernel(const long long* __restrict__ p, int cnt, int n) {
    int i = blockIdx.x * blockDim.x + threadIdx.x;
    if (i < n) { g_deg[i] = 0; g_cur[i] = 0; }
    if (i == 0) g_total = 0;
    if (blockIdx.x == 0) {
        __shared__ int bad;
        if (threadIdx.x == 0) bad = 0;
        __syncthreads();
        int lb = 0;
        for (int j = threadIdx.x; j < cnt; j += blockDim.x) {
            long long v = p[j];
            if (v < 0 || v > 0x7fffffffLL) lb = 1;
        }
        if (lb) atomicOr(&bad, 1);
        __syncthreads();
        if (threadIdx.x == 0) g_flag = bad;
    }
}

__global__ void decode_count_kernel(const void* __restrict__ ei, int E) {
    int e = blockIdx.x * blockDim.x + threadIdx.x;
    if (e >= E) return;
    int s, d;
    if (g_flag) {
        const int* p = (const int*)ei;
        s = p[e]; d = p[E + e];
    } else {
        const long long* p = (const long long*)ei;
        s = (int)p[e]; d = (int)p[(size_t)E + e];
    }
    g_src[e] = s;
    g_dst[e] = d;
    atomicAdd(&g_deg[d], 1);
}

// fused: g_dis = rsqrt(deg+1); block-local scan of deg; block base grabbed
// from a global allocator (node ranges in arbitrary disjoint order — gather
// only needs each node's own contiguous range).
__global__ void dis_off_kernel(int n) {
    __shared__ int sh[256];
    __shared__ int base;
    int i = blockIdx.x * 256 + threadIdx.x;
    int v = 0;
    if (i < n) {
        v = g_deg[i];
        g_dis[i] = rsqrtf((float)(v + 1));
    }
    sh[threadIdx.x] = v;
    __syncthreads();
#pragma unroll
    for (int ofs = 1; ofs < 256; ofs <<= 1) {
        int t = (threadIdx.x >= ofs) ? sh[threadIdx.x - ofs] : 0;
        __syncthreads();
        sh[threadIdx.x] += t;
        __syncthreads();
    }
    if (threadIdx.x == 255) base = atomicAdd(&g_total, sh[255]);
    __syncthreads();
    if (i < n) g_off[i] = base + sh[threadIdx.x] - v;
}

__global__ void csr_scatter_kernel(int E) {
    int e = blockIdx.x * blockDim.x + threadIdx.x;
    if (e >= E) return;
    int s = g_src[e];
    int d = g_dst[e];
    int pos = g_off[d] + atomicAdd(&g_cur[d], 1);
    g_epack[pos] = make_int2(s, __float_as_int(g_dis[s] * g_dis[d]));
}

// ===================== packed-f32x2 GEMM ===================================
// Y[n,DOUT] = X[n,K] @ W[K,DOUT] (+b). 256 threads; thread tile R rows x 4
// cols held as 2 packed f32x2 accumulators per row.
// Dynamic smem: Ws[K*DOUT] floats, then Xs2[ROWS*K] u64 (x duplicated lo==hi).
template <int K, int DOUT, int R, bool BIAS>
__global__ __launch_bounds__(256) void gemm_kernel(
    const float* __restrict__ X, const float* __restrict__ W,
    const float* __restrict__ b, float* __restrict__ Y, int n)
{
    constexpr int CG = DOUT / 4;
    constexpr int RG = 256 / CG;
    constexpr int ROWS = RG * R;

    extern __shared__ char dyn[];
    float* Ws = (float*)dyn;                                  // K*DOUT floats
    unsigned long long* Xs2 = (unsigned long long*)(dyn + (size_t)K * DOUT * 4);

    const int t = threadIdx.x;
    const int row0 = blockIdx.x * ROWS;

    for (int i = t; i < K * DOUT / 4; i += 256)
        ((float4*)Ws)[i] = ((const float4*)W)[i];

    for (int i = t; i < ROWS * K / 4; i += 256) {
        int pos = i * 4;
        int r = pos / K;
        int k = pos % K;
        int gr = row0 + r;
        float4 v = make_float4(0.f, 0.f, 0.f, 0.f);
        if (gr < n) v = *(const float4*)&X[(size_t)gr * K + k];
        unsigned long long d0, d1, d2, d3;
        asm("mov.b64 %0, {%1, %1};" : "=l"(d0) : "f"(v.x));
        asm("mov.b64 %0, {%1, %1};" : "=l"(d1) : "f"(v.y));
        asm("mov.b64 %0, {%1, %1};" : "=l"(d2) : "f"(v.z));
        asm("mov.b64 %0, {%1, %1};" : "=l"(d3) : "f"(v.w));
        unsigned long long* p = &Xs2[r * K + k];
        p[0] = d0; p[1] = d1; p[2] = d2; p[3] = d3;
    }
    __syncthreads();

    const int cg = t % CG;
    const int rg = t / CG;

    unsigned long long acc[R][2];
#pragma unroll
    for (int r = 0; r < R; r++) { acc[r][0] = 0ull; acc[r][1] = 0ull; }

#pragma unroll 4
    for (int k = 0; k < K; k++) {
        ulonglong2 w = *(const ulonglong2*)&Ws[k * DOUT + cg * 4];
#pragma unroll
        for (int r = 0; r < R; r++) {
            unsigned long long x2 = Xs2[(rg * R + r) * K + k];
            asm("fma.rn.f32x2 %0, %1, %2, %0;" : "+l"(acc[r][0]) : "l"(x2), "l"(w.x));
            asm("fma.rn.f32x2 %0, %1, %2, %0;" : "+l"(acc[r][1]) : "l"(x2), "l"(w.y));
        }
    }

    float4 bb = make_float4(0.f, 0.f, 0.f, 0.f);
    if (BIAS) bb = *(const float4*)&b[cg * 4];

#pragma unroll
    for (int r = 0; r < R; r++) {
        int gr = row0 + rg * R + r;
        if (gr < n) {
            float o0, o1, o2, o3;
            asm("mov.b64 {%0, %1}, %2;" : "=f"(o0), "=f"(o1) : "l"(acc[r][0]));
            asm("mov.b64 {%0, %1}, %2;" : "=f"(o2), "=f"(o3) : "l"(acc[r][1]));
            *(float4*)&Y[(size_t)gr * DOUT + cg * 4] =
                make_float4(o0 + bb.x, o1 + bb.y, o2 + bb.z, o3 + bb.w);
        }
    }
}

// ===================== CSR gather aggregation ==============================
// 16 threads per node (one float4 column each), 4-deep unroll: 4 independent
// epack loads then 4 independent H gathers in flight per trip.
// out[i] = (relu)(sum_e h[src_e]*norm_e + h[i]*dis_i^2 (+ b))
template <bool BIAS, bool RELU>
__global__ __launch_bounds__(256) void agg_gather_kernel(
    const float* __restrict__ H, const float* __restrict__ b,
    float* __restrict__ out, int n)
{
    int node = blockIdx.x * 16 + (threadIdx.x >> 4);
    int c = threadIdx.x & 15;
    if (node >= n) return;

    const float4* H4 = (const float4*)H;
    float dis = g_dis[node];
    float s2 = dis * dis;
    float4 hv = H4[(size_t)node * 16 + c];   // self-loop row, issued early

    int beg = g_off[node];
    int end = beg + g_deg[node];

    float4 acc;
    acc.x = hv.x * s2; acc.y = hv.y * s2;
    acc.z = hv.z * s2; acc.w = hv.w * s2;
    if (BIAS) {
        float4 bb = *(const float4*)&b[c * 4];
        acc.x += bb.x; acc.y += bb.y; acc.z += bb.z; acc.w += bb.w;
    }

    int e = beg;
    for (; e + 3 < end; e += 4) {
        int2 p0 = g_epack[e];
        int2 p1 = g_epack[e + 1];
        int2 p2 = g_epack[e + 2];
        int2 p3 = g_epack[e + 3];
        float4 h0 = H4[(size_t)p0.x * 16 + c];
        float4 h1 = H4[(size_t)p1.x * 16 + c];
        float4 h2 = H4[(size_t)p2.x * 16 + c];
        float4 h3 = H4[(size_t)p3.x * 16 + c];
        float n0 = __int_as_float(p0.y);
        float n1 = __int_as_float(p1.y);
        float n2 = __int_as_float(p2.y);
        float n3 = __int_as_float(p3.y);
        acc.x += h0.x * n0; acc.y += h0.y * n0; acc.z += h0.z * n0; acc.w += h0.w * n0;
        acc.x += h1.x * n1; acc.y += h1.y * n1; acc.z += h1.z * n1; acc.w += h1.w * n1;
        acc.x += h2.x * n2; acc.y += h2.y * n2; acc.z += h2.z * n2; acc.w += h2.w * n2;
        acc.x += h3.x * n3; acc.y += h3.y * n3; acc.z += h3.z * n3; acc.w += h3.w * n3;
    }
    if (e + 1 < end) {
        int2 p0 = g_epack[e];
        int2 p1 = g_epack[e + 1];
        float4 h0 = H4[(size_t)p0.x * 16 + c];
        float4 h1 = H4[(size_t)p1.x * 16 + c];
        float n0 = __int_as_float(p0.y);
        float n1 = __int_as_float(p1.y);
        acc.x += h0.x * n0; acc.y += h0.y * n0; acc.z += h0.z * n0; acc.w += h0.w * n0;
        acc.x += h1.x * n1; acc.y += h1.y * n1; acc.z += h1.z * n1; acc.w += h1.w * n1;
        e += 2;
    }
    if (e < end) {
        int2 p0 = g_epack[e];
        float4 h0 = H4[(size_t)p0.x * 16 + c];
        float n0 = __int_as_float(p0.y);
        acc.x += h0.x * n0; acc.y += h0.y * n0; acc.z += h0.z * n0; acc.w += h0.w * n0;
    }

    if (RELU) {
        acc.x = fmaxf(acc.x, 0.f); acc.y = fmaxf(acc.y, 0.f);
        acc.z = fmaxf(acc.z, 0.f); acc.w = fmaxf(acc.w, 0.f);
    }
    ((float4*)out)[(size_t)node * 16 + c] = acc;
}

static inline int ceil_div(long long a, int bsz) { return (int)((a + bsz - 1) / bsz); }

extern "C" void kernel_launch(void* const* d_in, const int* in_sizes, int n_in,
                              void* d_out, int out_size)
{
    const float* x  = (const float*)d_in[0];
    const void*  ei = d_in[1];
    const float* W1 = (const float*)d_in[2];
    const float* b1 = (const float*)d_in[3];
    const float* W2 = (const float*)d_in[4];
    const float* b2 = (const float*)d_in[5];
    const float* W3 = (const float*)d_in[6];
    const float* b3 = (const float*)d_in[7];
    const float* W4 = (const float*)d_in[8];
    const float* b4 = (const float*)d_in[9];

    const int N = in_sizes[0] / 128;
    const int E = in_sizes[1] / 2;

    float* out  = (float*)d_out;
    float* xhat = out;                       // [N,128]
    float* z    = out + (size_t)N * 128;     // [N,64]

    float* hbuf;  cudaGetSymbolAddress((void**)&hbuf, g_h);
    float* abuf;  cudaGetSymbolAddress((void**)&abuf, g_buf);

    // dynamic smem: Ws (K*DOUT*4) + Xs2 (ROWS*K*8)
    const int SM_L1 = 128 * 64 * 4 + 64 * 128 * 8;   // 96K
    const int SM_L2 = 64 * 64 * 4 + 64 * 64 * 8;     // 48K
    const int SM_L4 = 64 * 128 * 4 + 32 * 64 * 8;    // 48K
    static bool attr_done = false;
    if (!attr_done) {
        cudaFuncSetAttribute(gemm_kernel<128, 64, 4, false>,
                             cudaFuncAttributeMaxDynamicSharedMemorySize, SM_L1);
        cudaFuncSetAttribute(gemm_kernel<64, 64, 4, false>,
                             cudaFuncAttributeMaxDynamicSharedMemorySize, SM_L2);
        cudaFuncSetAttribute(gemm_kernel<64, 128, 4, true>,
                             cudaFuncAttributeMaxDynamicSharedMemorySize, SM_L4);
        attr_done = true;
    }

    const int nb = ceil_div(N, 256);
    const int ab = ceil_div(N, 16);          // agg: 16 nodes per 256-thr block

    // --- graph prep: 4 launches ---
    detect_zero_kernel<<<nb, 256>>>((const long long*)ei, 4096, N);
    decode_count_kernel<<<ceil_div(E, 256), 256>>>(ei, E);
    dis_off_kernel<<<nb, 256>>>(N);
    csr_scatter_kernel<<<ceil_div(E, 256), 256>>>(E);

    // --- layer 1 ---
    gemm_kernel<128, 64, 4, false><<<ceil_div(N, 64), 256, SM_L1>>>(x, W1, nullptr, hbuf, N);
    agg_gather_kernel<true, true><<<ab, 256>>>(hbuf, b1, abuf, N);   // 6th launch (profiled)

    // --- layer 2 ---
    gemm_kernel<64, 64, 4, false><<<ceil_div(N, 64), 256, SM_L2>>>(abuf, W2, nullptr, hbuf, N);
    agg_gather_kernel<true, true><<<ab, 256>>>(hbuf, b2, z, N);

    // --- layer 3 ---
    gemm_kernel<64, 64, 4, false><<<ceil_div(N, 64), 256, SM_L2>>>(z, W3, nullptr, hbuf, N);
    agg_gather_kernel<true, true><<<ab, 256>>>(hbuf, b3, abuf, N);

    // --- layer 4: aggregate first (A(XW) == (AX)W), then GEMM to 128 ---
    agg_gather_kernel<false, false><<<ab, 256>>>(abuf, nullptr, hbuf, N);
    gemm_kernel<64, 128, 4, true><<<ceil_div(N, 32), 256, SM_L4>>>(hbuf, W4, b4, xhat, N);
}

// round 9
// speedup vs baseline: 1.1288x; 1.0379x over previous
#include <cuda_runtime.h>
#include <cstdint>

// ---------------------------------------------------------------------------
// DOMINANT 4-layer GCN autoencoder.
// Norm-factored formulation: Hs = (X@W)*dis_row, so
//   out[d] = dis_d * (sum_e Hs[src_e] + Hs[d]) + b
// Edge records carry ONLY src (4B). CSR gather aggregation (16 thr/node,
// 4-deep unroll, no atomics in hot path) + packed-f32x2 (FFMA2) GEMMs.
//   L1: Hs=x@W1*dis;    abuf = relu(dis*acc + b1)
//   L2: Hs=abuf@W2*dis; z    = relu(dis*acc + b2)
//   L3: Hs=z@W3*dis;    abuf = relu(dis*acc + b3) * dis   (pre-scaled for L4)
//   L4: hbuf=dis*acc(abuf);  x_hat = hbuf@W4 + b4          (A(XW) == (AX)W)
//   out = concat(x_hat[N,128], z[N,64])
// ---------------------------------------------------------------------------

#define MAXN 50048
#define MAXE 640000

__device__ float g_h[(size_t)MAXN * 64];    // scaled post-GEMM features
__device__ float g_buf[(size_t)MAXN * 64];  // layer outputs
__device__ float g_dis[MAXN];               // rsqrt(deg+1)
__device__ int   g_deg[MAXN];               // in-degree (edges only)
__device__ int   g_off[MAXN];               // CSR slot base per node
__device__ int   g_cur[MAXN];               // scatter cursors
__device__ int2  g_sd[MAXE];                // decoded (src, dst)
__device__ int   g_esrc[MAXE];              // CSR slot: src only
__device__ int   g_flag;                    // 1 => edge_index is int32
__device__ int   g_total;                   // global slot allocator

// ========================= graph prep kernels ==============================
// zero g_deg + g_cur + g_total; block 0 also detects edge dtype (int64 data
// has all values < 50000; int32 reinterpreted as int64 -> huge values).
__global__ void detect_zero_kernel(const long long* __restrict__ p, int cnt, int n) {
    int i = blockIdx.x * blockDim.x + threadIdx.x;
    if (i < n) { g_deg[i] = 0; g_cur[i] = 0; }
    if (i == 0) g_total = 0;
    if (blockIdx.x == 0) {
        __shared__ int bad;
        if (threadIdx.x == 0) bad = 0;
        __syncthreads();
        int lb = 0;
        for (int j = threadIdx.x; j < cnt; j += blockDim.x) {
            long long v = p[j];
            if (v < 0 || v > 0x7fffffffLL) lb = 1;
        }
        if (lb) atomicOr(&bad, 1);
        __syncthreads();
        if (threadIdx.x == 0) g_flag = bad;
    }
}

__global__ void decode_count_kernel(const void* __restrict__ ei, int E) {
    int e = blockIdx.x * blockDim.x + threadIdx.x;
    if (e >= E) return;
    int s, d;
    if (g_flag) {
        const int* p = (const int*)ei;
        s = p[e]; d = p[E + e];
    } else {
        const long long* p = (const long long*)ei;
        s = (int)p[e]; d = (int)p[(size_t)E + e];
    }
    g_sd[e] = make_int2(s, d);
    atomicAdd(&g_deg[d], 1);
}

// fused: g_dis = rsqrt(deg+1); block-local scan of deg; block base grabbed
// from a global allocator (node ranges land in arbitrary disjoint order —
// gather only needs each node's own contiguous range).
__global__ void dis_off_kernel(int n) {
    __shared__ int sh[256];
    __shared__ int base;
    int i = blockIdx.x * 256 + threadIdx.x;
    int v = 0;
    if (i < n) {
        v = g_deg[i];
        g_dis[i] = rsqrtf((float)(v + 1));
    }
    sh[threadIdx.x] = v;
    __syncthreads();
#pragma unroll
    for (int ofs = 1; ofs < 256; ofs <<= 1) {
        int t = (threadIdx.x >= ofs) ? sh[threadIdx.x - ofs] : 0;
        __syncthreads();
        sh[threadIdx.x] += t;
        __syncthreads();
    }
    if (threadIdx.x == 255) base = atomicAdd(&g_total, sh[255]);
    __syncthreads();
    if (i < n) g_off[i] = base + sh[threadIdx.x] - v;
}

// scatter: slot gets ONLY src (no dis gathers, 4B store)
__global__ void csr_scatter_kernel(int E) {
    int e = blockIdx.x * blockDim.x + threadIdx.x;
    if (e >= E) return;
    int2 sd = g_sd[e];
    int pos = g_off[sd.y] + atomicAdd(&g_cur[sd.y], 1);
    g_esrc[pos] = sd.x;
}

// ===================== packed-f32x2 GEMM ===================================
// Y[n,DOUT] = X[n,K] @ W[K,DOUT] (+b) (*dis_row). 256 threads; thread tile
// R rows x 4 cols as 2 packed f32x2 accumulators per row.
// Dynamic smem: Ws[K*DOUT] floats, then Xs2[ROWS*K] u64 (x duplicated lo==hi).
template <int K, int DOUT, int R, bool BIAS, bool SCALE>
__global__ __launch_bounds__(256) void gemm_kernel(
    const float* __restrict__ X, const float* __restrict__ W,
    const float* __restrict__ b, float* __restrict__ Y, int n)
{
    constexpr int CG = DOUT / 4;
    constexpr int RG = 256 / CG;
    constexpr int ROWS = RG * R;

    extern __shared__ char dyn[];
    float* Ws = (float*)dyn;                                  // K*DOUT floats
    unsigned long long* Xs2 = (unsigned long long*)(dyn + (size_t)K * DOUT * 4);

    const int t = threadIdx.x;
    const int row0 = blockIdx.x * ROWS;

    for (int i = t; i < K * DOUT / 4; i += 256)
        ((float4*)Ws)[i] = ((const float4*)W)[i];

    for (int i = t; i < ROWS * K / 4; i += 256) {
        int pos = i * 4;
        int r = pos / K;
        int k = pos % K;
        int gr = row0 + r;
        float4 v = make_float4(0.f, 0.f, 0.f, 0.f);
        if (gr < n) v = *(const float4*)&X[(size_t)gr * K + k];
        unsigned long long d0, d1, d2, d3;
        asm("mov.b64 %0, {%1, %1};" : "=l"(d0) : "f"(v.x));
        asm("mov.b64 %0, {%1, %1};" : "=l"(d1) : "f"(v.y));
        asm("mov.b64 %0, {%1, %1};" : "=l"(d2) : "f"(v.z));
        asm("mov.b64 %0, {%1, %1};" : "=l"(d3) : "f"(v.w));
        unsigned long long* p = &Xs2[r * K + k];
        p[0] = d0; p[1] = d1; p[2] = d2; p[3] = d3;
    }
    __syncthreads();

    const int cg = t % CG;
    const int rg = t / CG;

    unsigned long long acc[R][2];
#pragma unroll
    for (int r = 0; r < R; r++) { acc[r][0] = 0ull; acc[r][1] = 0ull; }

#pragma unroll 4
    for (int k = 0; k < K; k++) {
        ulonglong2 w = *(const ulonglong2*)&Ws[k * DOUT + cg * 4];
#pragma unroll
        for (int r = 0; r < R; r++) {
            unsigned long long x2 = Xs2[(rg * R + r) * K + k];
            asm("fma.rn.f32x2 %0, %1, %2, %0;" : "+l"(acc[r][0]) : "l"(x2), "l"(w.x));
            asm("fma.rn.f32x2 %0, %1, %2, %0;" : "+l"(acc[r][1]) : "l"(x2), "l"(w.y));
        }
    }

    float4 bb = make_float4(0.f, 0.f, 0.f, 0.f);
    if (BIAS) bb = *(const float4*)&b[cg * 4];

#pragma unroll
    for (int r = 0; r < R; r++) {
        int gr = row0 + rg * R + r;
        if (gr < n) {
            float o0, o1, o2, o3;
            asm("mov.b64 {%0, %1}, %2;" : "=f"(o0), "=f"(o1) : "l"(acc[r][0]));
            asm("mov.b64 {%0, %1}, %2;" : "=f"(o2), "=f"(o3) : "l"(acc[r][1]));
            float sc = SCALE ? g_dis[gr] : 1.0f;
            *(float4*)&Y[(size_t)gr * DOUT + cg * 4] =
                make_float4(o0 * sc + bb.x, o1 * sc + bb.y,
                            o2 * sc + bb.z, o3 * sc + bb.w);
        }
    }
}

// ===================== CSR gather aggregation ==============================
// 16 threads per node (one float4 column each), 4-deep unroll.
// Input Hs already carries src scaling; out = (relu)(dis_node*(Hs[node] +
// sum_e Hs[src_e]) (+b)) (*dis_node if SCALE_OUT).
template <bool BIAS, bool RELU, bool SCALE_OUT>
__global__ __launch_bounds__(256) void agg_gather_kernel(
    const float* __restrict__ H, const float* __restrict__ b,
    float* __restrict__ out, int n)
{
    int node = blockIdx.x * 16 + (threadIdx.x >> 4);
    int c = threadIdx.x & 15;
    if (node >= n) return;

    const float4* H4 = (const float4*)H;
    float dis = g_dis[node];
    float4 acc = H4[(size_t)node * 16 + c];   // self term, issued early

    int beg = g_off[node];
    int end = beg + g_deg[node];

    int e = beg;
    for (; e + 3 < end; e += 4) {
        int s0 = g_esrc[e];
        int s1 = g_esrc[e + 1];
        int s2 = g_esrc[e + 2];
        int s3 = g_esrc[e + 3];
        float4 h0 = H4[(size_t)s0 * 16 + c];
        float4 h1 = H4[(size_t)s1 * 16 + c];
        float4 h2 = H4[(size_t)s2 * 16 + c];
        float4 h3 = H4[(size_t)s3 * 16 + c];
        acc.x += h0.x; acc.y += h0.y; acc.z += h0.z; acc.w += h0.w;
        acc.x += h1.x; acc.y += h1.y; acc.z += h1.z; acc.w += h1.w;
        acc.x += h2.x; acc.y += h2.y; acc.z += h2.z; acc.w += h2.w;
        acc.x += h3.x; acc.y += h3.y; acc.z += h3.z; acc.w += h3.w;
    }
    if (e + 1 < end) {
        int s0 = g_esrc[e];
        int s1 = g_esrc[e + 1];
        float4 h0 = H4[(size_t)s0 * 16 + c];
        float4 h1 = H4[(size_t)s1 * 16 + c];
        acc.x += h0.x; acc.y += h0.y; acc.z += h0.z; acc.w += h0.w;
        acc.x += h1.x; acc.y += h1.y; acc.z += h1.z; acc.w += h1.w;
        e += 2;
    }
    if (e < end) {
        int s0 = g_esrc[e];
        float4 h0 = H4[(size_t)s0 * 16 + c];
        acc.x += h0.x; acc.y += h0.y; acc.z += h0.z; acc.w += h0.w;
    }

    float4 r;
    r.x = acc.x * dis; r.y = acc.y * dis;
    r.z = acc.z * dis; r.w = acc.w * dis;
    if (BIAS) {
        float4 bb = *(const float4*)&b[c * 4];
        r.x += bb.x; r.y += bb.y; r.z += bb.z; r.w += bb.w;
    }
    if (RELU) {
        r.x = fmaxf(r.x, 0.f); r.y = fmaxf(r.y, 0.f);
        r.z = fmaxf(r.z, 0.f); r.w = fmaxf(r.w, 0.f);
    }
    if (SCALE_OUT) {
        r.x *= dis; r.y *= dis; r.z *= dis; r.w *= dis;
    }
    ((float4*)out)[(size_t)node * 16 + c] = r;
}

static inline int ceil_div(long long a, int bsz) { return (int)((a + bsz - 1) / bsz); }

extern "C" void kernel_launch(void* const* d_in, const int* in_sizes, int n_in,
                              void* d_out, int out_size)
{
    const float* x  = (const float*)d_in[0];
    const void*  ei = d_in[1];
    const float* W1 = (const float*)d_in[2];
    const float* b1 = (const float*)d_in[3];
    const float* W2 = (const float*)d_in[4];
    const float* b2 = (const float*)d_in[5];
    const float* W3 = (const float*)d_in[6];
    const float* b3 = (const float*)d_in[7];
    const float* W4 = (const float*)d_in[8];
    const float* b4 = (const float*)d_in[9];

    const int N = in_sizes[0] / 128;
    const int E = in_sizes[1] / 2;

    float* out  = (float*)d_out;
    float* xhat = out;                       // [N,128]
    float* z    = out + (size_t)N * 128;     // [N,64]

    float* hbuf;  cudaGetSymbolAddress((void**)&hbuf, g_h);
    float* abuf;  cudaGetSymbolAddress((void**)&abuf, g_buf);

    // dynamic smem: Ws (K*DOUT*4) + Xs2 (ROWS*K*8)
    const int SM_L1 = 128 * 64 * 4 + 64 * 128 * 8;   // 96K
    const int SM_L2 = 64 * 64 * 4 + 64 * 64 * 8;     // 48K
    const int SM_L4 = 64 * 128 * 4 + 32 * 64 * 8;    // 48K
    static bool attr_done = false;
    if (!attr_done) {
        cudaFuncSetAttribute(gemm_kernel<128, 64, 4, false, true>,
                             cudaFuncAttributeMaxDynamicSharedMemorySize, SM_L1);
        cudaFuncSetAttribute(gemm_kernel<64, 64, 4, false, true>,
                             cudaFuncAttributeMaxDynamicSharedMemorySize, SM_L2);
        cudaFuncSetAttribute(gemm_kernel<64, 128, 4, true, false>,
                             cudaFuncAttributeMaxDynamicSharedMemorySize, SM_L4);
        attr_done = true;
    }

    const int nb = ceil_div(N, 256);
    const int ab = ceil_div(N, 16);          // agg: 16 nodes per 256-thr block

    // --- graph prep: 4 launches ---
    detect_zero_kernel<<<nb, 256>>>((const long long*)ei, 4096, N);
    decode_count_kernel<<<ceil_div(E, 256), 256>>>(ei, E);
    dis_off_kernel<<<nb, 256>>>(N);
    csr_scatter_kernel<<<ceil_div(E, 256), 256>>>(E);

    // --- layer 1: Hs = (x@W1)*dis; abuf = relu(dis*acc + b1) ---
    gemm_kernel<128, 64, 4, false, true><<<ceil_div(N, 64), 256, SM_L1>>>(x, W1, nullptr, hbuf, N);
    agg_gather_kernel<true, true, false><<<ab, 256>>>(hbuf, b1, abuf, N);  // 6th launch

    // --- layer 2: Hs = (abuf@W2)*dis; z = relu(dis*acc + b2) ---
    gemm_kernel<64, 64, 4, false, true><<<ceil_div(N, 64), 256, SM_L2>>>(abuf, W2, nullptr, hbuf, N);
    agg_gather_kernel<true, true, false><<<ab, 256>>>(hbuf, b2, z, N);

    // --- layer 3: Hs = (z@W3)*dis; abuf = relu(dis*acc + b3)*dis ---
    gemm_kernel<64, 64, 4, false, true><<<ceil_div(N, 64), 256, SM_L2>>>(z, W3, nullptr, hbuf, N);
    agg_gather_kernel<true, true, true><<<ab, 256>>>(hbuf, b3, abuf, N);

    // --- layer 4: hbuf = dis*acc(abuf); x_hat = hbuf@W4 + b4 ---
    agg_gather_kernel<false, false, false><<<ab, 256>>>(abuf, nullptr, hbuf, N);
    gemm_kernel<64, 128, 4, true, false><<<ceil_div(N, 32), 256, SM_L4>>>(hbuf, W4, b4, xhat, N);
}

// round 10
// speedup vs baseline: 1.2223x; 1.0828x over previous
#include <cuda_runtime.h>
#include <cstdint>

// ---------------------------------------------------------------------------
// DOMINANT 4-layer GCN autoencoder.
// Norm-factored: Hs = (X@W)*dis_row  =>  out[d] = dis_d*(sum Hs[src] + Hs[d]) + b
// Edge slots carry ONLY src (4B). CSR gather aggregation (16 thr/node, 4-deep
// unroll, no atomics in hot path) + packed-f32x2 (FFMA2) GEMMs.
// gemm1 runs on a second stream, overlapped with dis_off + csr_scatter
// (its epilogue computes dis inline from g_deg).
//   L1: Hs=x@W1*dis;    abuf = relu(dis*acc + b1)
//   L2: Hs=abuf@W2*dis; z    = relu(dis*acc + b2)
//   L3: Hs=z@W3*dis;    abuf = relu(dis*acc + b3) * dis   (pre-scaled for L4)
//   L4: hbuf=dis*acc(abuf);  x_hat = hbuf@W4 + b4          (A(XW) == (AX)W)
//   out = concat(x_hat[N,128], z[N,64])
// ---------------------------------------------------------------------------

#define MAXN 50048
#define MAXE 640000

__device__ float g_h[(size_t)MAXN * 64];    // scaled post-GEMM features
__device__ float g_buf[(size_t)MAXN * 64];  // layer outputs
__device__ float g_dis[MAXN];               // rsqrt(deg+1)
__device__ int   g_deg[MAXN];               // in-degree (edges only)
__device__ int   g_off[MAXN];               // CSR slot base per node
__device__ int   g_cur[MAXN];               // scatter cursors (pre-init to off)
__device__ int2  g_sd[MAXE];                // decoded (src, dst)
__device__ int   g_esrc[MAXE];              // CSR slot: src only
__device__ int   g_flag;                    // 1 => edge_index is int32
__device__ int   g_total;                   // global slot allocator

// ========================= graph prep kernels ==============================
// zero g_deg + g_total; block 0 also detects edge dtype (int64 data has all
// values < 50000; int32 reinterpreted as int64 -> huge values w.h.p.).
__global__ void detect_zero_kernel(const long long* __restrict__ p, int cnt, int n) {
    int i = blockIdx.x * blockDim.x + threadIdx.x;
    if (i < n) g_deg[i] = 0;
    if (i == 0) g_total = 0;
    if (blockIdx.x == 0) {
        __shared__ int bad;
        if (threadIdx.x == 0) bad = 0;
        __syncthreads();
        int lb = 0;
        for (int j = threadIdx.x; j < cnt; j += blockDim.x) {
            long long v = p[j];
            if (v < 0 || v > 0x7fffffffLL) lb = 1;
        }
        if (lb) atomicOr(&bad, 1);
        __syncthreads();
        if (threadIdx.x == 0) g_flag = bad;
    }
}

__global__ void decode_count_kernel(const void* __restrict__ ei, int E) {
    int e = blockIdx.x * blockDim.x + threadIdx.x;
    if (e >= E) return;
    int s, d;
    if (g_flag) {
        const int* p = (const int*)ei;
        s = p[e]; d = p[E + e];
    } else {
        const long long* p = (const long long*)ei;
        s = (int)p[e]; d = (int)p[(size_t)E + e];
    }
    g_sd[e] = make_int2(s, d);
    atomicAdd(&g_deg[d], 1);
}

// fused: g_dis = rsqrt(deg+1); block-local scan of deg; block base grabbed
// from a global allocator (node ranges land in arbitrary disjoint order —
// gather only needs each node's own contiguous range). Cursor pre-init to
// the base offset so scatter needs a single atomic.
__global__ void dis_off_kernel(int n) {
    __shared__ int sh[256];
    __shared__ int base;
    int i = blockIdx.x * 256 + threadIdx.x;
    int v = 0;
    if (i < n) {
        v = g_deg[i];
        g_dis[i] = rsqrtf((float)(v + 1));
    }
    sh[threadIdx.x] = v;
    __syncthreads();
#pragma unroll
    for (int ofs = 1; ofs < 256; ofs <<= 1) {
        int t = (threadIdx.x >= ofs) ? sh[threadIdx.x - ofs] : 0;
        __syncthreads();
        sh[threadIdx.x] += t;
        __syncthreads();
    }
    if (threadIdx.x == 255) base = atomicAdd(&g_total, sh[255]);
    __syncthreads();
    if (i < n) {
        int o = base + sh[threadIdx.x] - v;
        g_off[i] = o;
        g_cur[i] = o;
    }
}

// scatter: single atomic returns slot directly
__global__ void csr_scatter_kernel(int E) {
    int e = blockIdx.x * blockDim.x + threadIdx.x;
    if (e >= E) return;
    int2 sd = g_sd[e];
    int pos = atomicAdd(&g_cur[sd.y], 1);
    g_esrc[pos] = sd.x;
}

// ===================== packed-f32x2 GEMM ===================================
// Y[n,DOUT] = X[n,K] @ W[K,DOUT] (+b) (*scale_row).
// SCALE_MODE: 0 = none, 1 = multiply by g_dis[row], 2 = multiply by
// rsqrt(g_deg[row]+1) computed inline (no dependency on dis_off).
// 256 threads; thread tile R rows x 4 cols as 2 packed f32x2 accumulators.
// Dynamic smem: Ws[K*DOUT] floats, then Xs2[ROWS*K] u64 (x duplicated lo==hi).
template <int K, int DOUT, int R, bool BIAS, int SCALE_MODE>
__global__ __launch_bounds__(256) void gemm_kernel(
    const float* __restrict__ X, const float* __restrict__ W,
    const float* __restrict__ b, float* __restrict__ Y, int n)
{
    constexpr int CG = DOUT / 4;
    constexpr int RG = 256 / CG;
    constexpr int ROWS = RG * R;

    extern __shared__ char dyn[];
    float* Ws = (float*)dyn;                                  // K*DOUT floats
    unsigned long long* Xs2 = (unsigned long long*)(dyn + (size_t)K * DOUT * 4);

    const int t = threadIdx.x;
    const int row0 = blockIdx.x * ROWS;

    for (int i = t; i < K * DOUT / 4; i += 256)
        ((float4*)Ws)[i] = ((const float4*)W)[i];

    for (int i = t; i < ROWS * K / 4; i += 256) {
        int pos = i * 4;
        int r = pos / K;
        int k = pos % K;
        int gr = row0 + r;
        float4 v = make_float4(0.f, 0.f, 0.f, 0.f);
        if (gr < n) v = *(const float4*)&X[(size_t)gr * K + k];
        unsigned long long d0, d1, d2, d3;
        asm("mov.b64 %0, {%1, %1};" : "=l"(d0) : "f"(v.x));
        asm("mov.b64 %0, {%1, %1};" : "=l"(d1) : "f"(v.y));
        asm("mov.b64 %0, {%1, %1};" : "=l"(d2) : "f"(v.z));
        asm("mov.b64 %0, {%1, %1};" : "=l"(d3) : "f"(v.w));
        unsigned long long* p = &Xs2[r * K + k];
        p[0] = d0; p[1] = d1; p[2] = d2; p[3] = d3;
    }
    __syncthreads();

    const int cg = t % CG;
    const int rg = t / CG;

    unsigned long long acc[R][2];
#pragma unroll
    for (int r = 0; r < R; r++) { acc[r][0] = 0ull; acc[r][1] = 0ull; }

#pragma unroll 4
    for (int k = 0; k < K; k++) {
        ulonglong2 w = *(const ulonglong2*)&Ws[k * DOUT + cg * 4];
#pragma unroll
        for (int r = 0; r < R; r++) {
            unsigned long long x2 = Xs2[(rg * R + r) * K + k];
            asm("fma.rn.f32x2 %0, %1, %2, %0;" : "+l"(acc[r][0]) : "l"(x2), "l"(w.x));
            asm("fma.rn.f32x2 %0, %1, %2, %0;" : "+l"(acc[r][1]) : "l"(x2), "l"(w.y));
        }
    }

    float4 bb = make_float4(0.f, 0.f, 0.f, 0.f);
    if (BIAS) bb = *(const float4*)&b[cg * 4];

#pragma unroll
    for (int r = 0; r < R; r++) {
        int gr = row0 + rg * R + r;
        if (gr < n) {
            float o0, o1, o2, o3;
            asm("mov.b64 {%0, %1}, %2;" : "=f"(o0), "=f"(o1) : "l"(acc[r][0]));
            asm("mov.b64 {%0, %1}, %2;" : "=f"(o2), "=f"(o3) : "l"(acc[r][1]));
            float sc = 1.0f;
            if (SCALE_MODE == 1) sc = g_dis[gr];
            if (SCALE_MODE == 2) sc = rsqrtf((float)(g_deg[gr] + 1));
            *(float4*)&Y[(size_t)gr * DOUT + cg * 4] =
                make_float4(o0 * sc + bb.x, o1 * sc + bb.y,
                            o2 * sc + bb.z, o3 * sc + bb.w);
        }
    }
}

// ===================== CSR gather aggregation ==============================
// 16 threads per node (one float4 column each), 4-deep unroll.
// Input Hs already carries src scaling; out = (relu)(dis_node*(Hs[node] +
// sum_e Hs[src_e]) (+b)) (*dis_node if SCALE_OUT).
template <bool BIAS, bool RELU, bool SCALE_OUT>
__global__ __launch_bounds__(256) void agg_gather_kernel(
    const float* __restrict__ H, const float* __restrict__ b,
    float* __restrict__ out, int n)
{
    int node = blockIdx.x * 16 + (threadIdx.x >> 4);
    int c = threadIdx.x & 15;
    if (node >= n) return;

    const float4* H4 = (const float4*)H;
    float dis = g_dis[node];
    float4 acc = H4[(size_t)node * 16 + c];   // self term, issued early

    int beg = g_off[node];
    int end = beg + g_deg[node];

    int e = beg;
    for (; e + 3 < end; e += 4) {
        int s0 = g_esrc[e];
        int s1 = g_esrc[e + 1];
        int s2 = g_esrc[e + 2];
        int s3 = g_esrc[e + 3];
        float4 h0 = H4[(size_t)s0 * 16 + c];
        float4 h1 = H4[(size_t)s1 * 16 + c];
        float4 h2 = H4[(size_t)s2 * 16 + c];
        float4 h3 = H4[(size_t)s3 * 16 + c];
        acc.x += h0.x; acc.y += h0.y; acc.z += h0.z; acc.w += h0.w;
        acc.x += h1.x; acc.y += h1.y; acc.z += h1.z; acc.w += h1.w;
        acc.x += h2.x; acc.y += h2.y; acc.z += h2.z; acc.w += h2.w;
        acc.x += h3.x; acc.y += h3.y; acc.z += h3.z; acc.w += h3.w;
    }
    if (e + 1 < end) {
        int s0 = g_esrc[e];
        int s1 = g_esrc[e + 1];
        float4 h0 = H4[(size_t)s0 * 16 + c];
        float4 h1 = H4[(size_t)s1 * 16 + c];
        acc.x += h0.x; acc.y += h0.y; acc.z += h0.z; acc.w += h0.w;
        acc.x += h1.x; acc.y += h1.y; acc.z += h1.z; acc.w += h1.w;
        e += 2;
    }
    if (e < end) {
        int s0 = g_esrc[e];
        float4 h0 = H4[(size_t)s0 * 16 + c];
        acc.x += h0.x; acc.y += h0.y; acc.z += h0.z; acc.w += h0.w;
    }

    float4 r;
    r.x = acc.x * dis; r.y = acc.y * dis;
    r.z = acc.z * dis; r.w = acc.w * dis;
    if (BIAS) {
        float4 bb = *(const float4*)&b[c * 4];
        r.x += bb.x; r.y += bb.y; r.z += bb.z; r.w += bb.w;
    }
    if (RELU) {
        r.x = fmaxf(r.x, 0.f); r.y = fmaxf(r.y, 0.f);
        r.z = fmaxf(r.z, 0.f); r.w = fmaxf(r.w, 0.f);
    }
    if (SCALE_OUT) {
        r.x *= dis; r.y *= dis; r.z *= dis; r.w *= dis;
    }
    ((float4*)out)[(size_t)node * 16 + c] = r;
}

static inline int ceil_div(long long a, int bsz) { return (int)((a + bsz - 1) / bsz); }

extern "C" void kernel_launch(void* const* d_in, const int* in_sizes, int n_in,
                              void* d_out, int out_size)
{
    const float* x  = (const float*)d_in[0];
    const void*  ei = d_in[1];
    const float* W1 = (const float*)d_in[2];
    const float* b1 = (const float*)d_in[3];
    const float* W2 = (const float*)d_in[4];
    const float* b2 = (const float*)d_in[5];
    const float* W3 = (const float*)d_in[6];
    const float* b3 = (const float*)d_in[7];
    const float* W4 = (const float*)d_in[8];
    const float* b4 = (const float*)d_in[9];

    const int N = in_sizes[0] / 128;
    const int E = in_sizes[1] / 2;

    float* out  = (float*)d_out;
    float* xhat = out;                       // [N,128]
    float* z    = out + (size_t)N * 128;     // [N,64]

    float* hbuf;  cudaGetSymbolAddress((void**)&hbuf, g_h);
    float* abuf;  cudaGetSymbolAddress((void**)&abuf, g_buf);

    // dynamic smem: Ws (K*DOUT*4) + Xs2 (ROWS*K*8)
    const int SM_L1 = 128 * 64 * 4 + 64 * 128 * 8;   // 96K
    const int SM_L2 = 64 * 64 * 4 + 64 * 64 * 8;     // 48K
    const int SM_L4 = 64 * 128 * 4 + 32 * 64 * 8;    // 48K

    static cudaStream_t s2 = nullptr;
    static cudaEvent_t ev_decode = nullptr, ev_gemm1 = nullptr;
    static bool init_done = false;
    if (!init_done) {
        cudaFuncSetAttribute(gemm_kernel<128, 64, 4, false, 2>,
                             cudaFuncAttributeMaxDynamicSharedMemorySize, SM_L1);
        cudaFuncSetAttribute(gemm_kernel<64, 64, 4, false, 1>,
                             cudaFuncAttributeMaxDynamicSharedMemorySize, SM_L2);
        cudaFuncSetAttribute(gemm_kernel<64, 128, 4, true, 0>,
                             cudaFuncAttributeMaxDynamicSharedMemorySize, SM_L4);
        cudaStreamCreateWithFlags(&s2, cudaStreamNonBlocking);
        cudaEventCreateWithFlags(&ev_decode, cudaEventDisableTiming);
        cudaEventCreateWithFlags(&ev_gemm1, cudaEventDisableTiming);
        init_done = true;
    }

    const int nb = ceil_div(N, 256);
    const int ab = ceil_div(N, 16);          // agg: 16 nodes per 256-thr block

    // --- prep head (main stream) ---
    detect_zero_kernel<<<nb, 256>>>((const long long*)ei, 4096, N);
    decode_count_kernel<<<ceil_div(E, 256), 256>>>(ei, E);
    cudaEventRecord(ev_decode, 0);

    // --- gemm1 on side stream (needs only g_deg + x + W1), overlapped with
    //     dis_off + csr_scatter on the main stream ---
    cudaStreamWaitEvent(s2, ev_decode, 0);
    gemm_kernel<128, 64, 4, false, 2><<<ceil_div(N, 64), 256, SM_L1, s2>>>(
        x, W1, nullptr, hbuf, N);
    cudaEventRecord(ev_gemm1, s2);

    dis_off_kernel<<<nb, 256>>>(N);
    csr_scatter_kernel<<<ceil_div(E, 256), 256>>>(E);
    cudaStreamWaitEvent(0, ev_gemm1, 0);

    // --- layer 1 agg ---
    agg_gather_kernel<true, true, false><<<ab, 256>>>(hbuf, b1, abuf, N);

    // --- layer 2 ---
    gemm_kernel<64, 64, 4, false, 1><<<ceil_div(N, 64), 256, SM_L2>>>(abuf, W2, nullptr, hbuf, N);
    agg_gather_kernel<true, true, false><<<ab, 256>>>(hbuf, b2, z, N);

    // --- layer 3 ---
    gemm_kernel<64, 64, 4, false, 1><<<ceil_div(N, 64), 256, SM_L2>>>(z, W3, nullptr, hbuf, N);
    agg_gather_kernel<true, true, true><<<ab, 256>>>(hbuf, b3, abuf, N);

    // --- layer 4: aggregate first (A(XW) == (AX)W), then GEMM to 128 ---
    agg_gather_kernel<false, false, false><<<ab, 256>>>(abuf, nullptr, hbuf, N);
    gemm_kernel<64, 128, 4, true, 0><<<ceil_div(N, 32), 256, SM_L4>>>(hbuf, W4, b4, xhat, N);
}